// round 9
// baseline (speedup 1.0000x reference)
#include <cuda_runtime.h>
#include <cuda_fp16.h>
#include <cstdint>
#include <cstddef>

// ---------------------------------------------------------------------------
// Problem constants
// ---------------------------------------------------------------------------
#define VOCAB 50257
#define DMODEL 768
#define NEXP 4
#define RRANK 32
#define BATCH 4
#define SEQ 512
#define NROWS (BATCH * SEQ)   // 2048

// ---------------------------------------------------------------------------
// Scratch (static device buffers; no cudaMalloc allowed)
// ---------------------------------------------------------------------------
__device__ __align__(256) float  g_x[NROWS * DMODEL];
__device__ __align__(256) __half g_h16[NROWS * DMODEL];
__device__ __align__(256) float  g_P[NROWS * NEXP * RRANK];
__device__ __align__(256) float  g_C[NROWS * RRANK];
__device__ __align__(256) int    g_E[NROWS];
__device__ __align__(256) __half g_Wh[(size_t)VOCAB * DMODEL];  // fp16 W_emb

__device__ __forceinline__ uint32_t smem_u32(const void* p) {
    uint32_t a;
    asm("{ .reg .u64 t; cvta.to.shared.u64 t, %1; cvt.u32.u64 %0, t; }"
        : "=r"(a) : "l"(p));
    return a;
}

__device__ __forceinline__ void cpasync16(uint32_t dst, const void* src, int szbytes) {
    asm volatile("cp.async.cg.shared.global [%0], [%1], 16, %2;"
                 :: "r"(dst), "l"(src), "r"(szbytes));
}
#define CP_COMMIT() asm volatile("cp.async.commit_group;" ::: "memory")
#define CP_WAIT2()  asm volatile("cp.async.wait_group 2;" ::: "memory")

__device__ __forceinline__ void ldsm_x4(uint32_t* r, uint32_t addr) {
    asm volatile("ldmatrix.sync.aligned.m8n8.x4.shared.b16 {%0,%1,%2,%3}, [%4];"
                 : "=r"(r[0]), "=r"(r[1]), "=r"(r[2]), "=r"(r[3]) : "r"(addr));
}

// ---------------------------------------------------------------------------
// Kernel 1: embedding gather + routing scores + input projection (all experts)
// ---------------------------------------------------------------------------
__global__ __launch_bounds__(160) void k_embed_route(
    const int* __restrict__ idx, const float* __restrict__ Wemb,
    const float* __restrict__ G, const float* __restrict__ Win) {
    __shared__ float xs[8][DMODEL];
    __shared__ float ssc[8][NEXP];
    __shared__ int tok[8];
    const int tid = threadIdx.x;
    const int row0 = blockIdx.x * 8;

    if (tid < 8) tok[tid] = idx[row0 + tid];
    __syncthreads();
    for (int i = tid; i < 8 * DMODEL; i += 160) {
        int rr = i / DMODEL, d = i - rr * DMODEL;
        float v = Wemb[(size_t)tok[rr] * DMODEL + d];
        xs[rr][d] = v;
        g_x[(size_t)(row0 + rr) * DMODEL + d] = v;
    }
    __syncthreads();

    const int j = tid;
    if (j < 132) {
        float acc[8];
#pragma unroll
        for (int rr = 0; rr < 8; rr++) acc[rr] = 0.0f;
        const float* wp;
        int stride;
        if (j < 128) { int e = j >> 5, r = j & 31; wp = Win + (size_t)e * DMODEL * RRANK + r; stride = RRANK; }
        else         { wp = G + (size_t)(j - 128) * DMODEL; stride = 1; }
        for (int d = 0; d < DMODEL; d += 4) {
            float w0 = wp[(size_t)d * stride];
            float w1 = wp[(size_t)(d + 1) * stride];
            float w2 = wp[(size_t)(d + 2) * stride];
            float w3 = wp[(size_t)(d + 3) * stride];
#pragma unroll
            for (int rr = 0; rr < 8; rr++) {
                float4 xv = *(const float4*)&xs[rr][d];
                acc[rr] = fmaf(xv.x, w0, acc[rr]);
                acc[rr] = fmaf(xv.y, w1, acc[rr]);
                acc[rr] = fmaf(xv.z, w2, acc[rr]);
                acc[rr] = fmaf(xv.w, w3, acc[rr]);
            }
        }
        if (j < 128) {
#pragma unroll
            for (int rr = 0; rr < 8; rr++)
                g_P[(size_t)(row0 + rr) * (NEXP * RRANK) + j] = acc[rr];
        } else {
#pragma unroll
            for (int rr = 0; rr < 8; rr++) ssc[rr][j - 128] = acc[rr];
        }
    }
    __syncthreads();
    if (tid < 8) {
        float best = ssc[tid][0];
        int be = 0;
#pragma unroll
        for (int e = 1; e < NEXP; e++)
            if (ssc[tid][e] > best) { best = ssc[tid][e]; be = e; }
        g_E[row0 + tid] = be;
    }
}

// ---------------------------------------------------------------------------
// Kernel 2 (merged): W_emb fp32->fp16 rounding on blocks [0, N-1) and the
// sequential recurrence on the last block (independent work, one launch:
// runtime = max of the two instead of sum).
// ---------------------------------------------------------------------------
#define RS_STEP(ST, EBASE) {                                                   \
    float a0 = 0.f, a1 = 0.f, a2 = 0.f, a3 = 0.f;                              \
    _Pragma("unroll")                                                          \
    for (int k = 0; k < 8; k++) {                                              \
        a0 = fmaf(__shfl_sync(0xffffffffu, ST, k     ), ws[(EBASE) + (k     ) * 32 + o], a0); \
        a1 = fmaf(__shfl_sync(0xffffffffu, ST, k +  8), ws[(EBASE) + (k +  8) * 32 + o], a1); \
        a2 = fmaf(__shfl_sync(0xffffffffu, ST, k + 16), ws[(EBASE) + (k + 16) * 32 + o], a2); \
        a3 = fmaf(__shfl_sync(0xffffffffu, ST, k + 24), ws[(EBASE) + (k + 24) * 32 + o], a3); \
    }                                                                          \
    cand = tanhf(p_cur + ((a0 + a1) + (a2 + a3)));                             \
    ST = cand; }

__global__ __launch_bounds__(256) void k_roundscan(
    const float* __restrict__ W, const float* __restrict__ Wrec) {
    if (blockIdx.x + 1 < gridDim.x) {
        // ---- rounding path: 8 elements per thread ----
        const size_t g = (size_t)blockIdx.x * 256 + threadIdx.x;
        const size_t ng = ((size_t)VOCAB * DMODEL) / 8;
        if (g >= ng) return;
        const float4 v0 = *((const float4*)W + g * 2);
        const float4 v1 = *((const float4*)W + g * 2 + 1);
        __half2 h[4];
        h[0] = __floats2half2_rn(v0.x, v0.y);
        h[1] = __floats2half2_rn(v0.z, v0.w);
        h[2] = __floats2half2_rn(v1.x, v1.y);
        h[3] = __floats2half2_rn(v1.z, v1.w);
        *((uint4*)g_Wh + g) = *(uint4*)h;
    } else {
        // ---- scan path: 4 warps, one per batch ----
        __shared__ float ws[NEXP * RRANK * RRANK];   // 16 KB
        const int tid = threadIdx.x;
        for (int i = tid; i < NEXP * RRANK * RRANK; i += 256) ws[i] = Wrec[i];
        __syncthreads();
        if (tid >= 128) return;
        const int b = tid >> 5;
        const int o = tid & 31;

        float st0 = 0.f, st1 = 0.f, st2 = 0.f, st3 = 0.f;
        const int base = b * SEQ;
        int   e_cur = g_E[base];
        int   e_nxt = g_E[base + 1];
        float p_cur = g_P[(size_t)base * 128 + e_cur * 32 + o];

        for (int t = 0; t < SEQ; t++) {
            float p_nxt = 0.f;
            int   e_nn = 0;
            if (t + 1 < SEQ) p_nxt = g_P[(size_t)(base + t + 1) * 128 + e_nxt * 32 + o];
            if (t + 2 < SEQ) e_nn = g_E[base + t + 2];

            float cand;
            switch (e_cur) {
                case 0: RS_STEP(st0, 0);    break;
                case 1: RS_STEP(st1, 1024); break;
                case 2: RS_STEP(st2, 2048); break;
                default: RS_STEP(st3, 3072); break;
            }
            g_C[(size_t)(base + t) * 32 + o] = cand;

            p_cur = p_nxt; e_cur = e_nxt; e_nxt = e_nn;
        }
    }
}

// ---------------------------------------------------------------------------
// Kernel 3: output projection + residual + LayerNorm -> fp16 h
// ---------------------------------------------------------------------------
__global__ __launch_bounds__(256) void k_outln(
    const float* __restrict__ Wout, const float* __restrict__ gamma,
    const float* __restrict__ beta) {
    __shared__ float csh[32];
    __shared__ float rs[8], rs2[8];
    const int row = blockIdx.x;
    const int tid = threadIdx.x;
    if (tid < 32) csh[tid] = g_C[(size_t)row * 32 + tid];
    const int e = g_E[row];
    __syncthreads();

    const float* wb = Wout + (size_t)e * RRANK * DMODEL;
    float y[3];
    float s = 0.f, s2 = 0.f;
#pragma unroll
    for (int ii = 0; ii < 3; ii++) {
        int d = tid + ii * 256;
        float acc = g_x[(size_t)row * DMODEL + d];
#pragma unroll
        for (int r = 0; r < 32; r++)
            acc = fmaf(csh[r], wb[r * DMODEL + d], acc);
        y[ii] = acc;
        s += acc;
        s2 = fmaf(acc, acc, s2);
    }
#pragma unroll
    for (int off = 16; off; off >>= 1) {
        s  += __shfl_xor_sync(0xffffffffu, s, off);
        s2 += __shfl_xor_sync(0xffffffffu, s2, off);
    }
    if ((tid & 31) == 0) { rs[tid >> 5] = s; rs2[tid >> 5] = s2; }
    __syncthreads();
    float S = 0.f, S2 = 0.f;
#pragma unroll
    for (int w = 0; w < 8; w++) { S += rs[w]; S2 += rs2[w]; }
    const float mean = S * (1.0f / DMODEL);
    const float var = S2 * (1.0f / DMODEL) - mean * mean;
    const float inv = rsqrtf(var + 1e-5f);
#pragma unroll
    for (int ii = 0; ii < 3; ii++) {
        int d = tid + ii * 256;
        float hv = (y[ii] - mean) * inv * gamma[d] + beta[d];
        g_h16[(size_t)row * DMODEL + d] = __float2half_rn(hv);
    }
}

// ---------------------------------------------------------------------------
// Kernel 4: logits = h @ W_emb^T, fp16 mma.sync.m16n8k16 (fp32 accumulate).
//   CTA 128x128, 8 warps (2m x 4n), warp tile 64x32, 2 CTAs per SM:
//   a co-resident independent CTA hides epilogue/barrier/prologue exposure.
//   K chunk 64, 3-stage cp.async (110.6 KB smem/CTA). ldmatrix fragments.
// ---------------------------------------------------------------------------
#define GTM 128
#define GTN 128
#define GKB 64
#define NKB (DMODEL / GKB)          // 12
#define ASTRH 72                    // halves per row
#define A_STAGE_H (GTM * ASTRH)     // 9216 halves
#define B_STAGE_H (GTN * ASTRH)     // 9216 halves
#define NSTAGE 3
#define BOFFH (NSTAGE * A_STAGE_H)
#define GEMM_SMEM (NSTAGE * (A_STAGE_H + B_STAGE_H) * 2)   // 110,592 B

__device__ __forceinline__ void mma_f16_16n8k16(
    float* c, const uint32_t* a, const uint32_t* b) {
    asm volatile(
        "mma.sync.aligned.m16n8k16.row.col.f32.f16.f16.f32 "
        "{%0,%1,%2,%3}, {%4,%5,%6,%7}, {%8,%9}, {%0,%1,%2,%3};"
        : "+f"(c[0]), "+f"(c[1]), "+f"(c[2]), "+f"(c[3])
        : "r"(a[0]), "r"(a[1]), "r"(a[2]), "r"(a[3]), "r"(b[0]), "r"(b[1]));
}

__global__ __launch_bounds__(256, 2) void k_gemm(
    const __half* __restrict__ A, const __half* __restrict__ Bw,
    float* __restrict__ C) {
    extern __shared__ __half smh[];
    const uint32_t smb = smem_u32(smh);

    const int tid = threadIdx.x;
    const int wid = tid >> 5, lane = tid & 31;
    const int wm = wid & 1, wn = wid >> 1;       // 2(m) x 4(n)
    const int lr = lane >> 2, lc = lane & 3;
    const int m0 = blockIdx.x * GTM;
    const int n0 = blockIdx.y * GTN;

    float acc[4][4][4];
#pragma unroll
    for (int mf = 0; mf < 4; mf++)
#pragma unroll
        for (int nf = 0; nf < 4; nf++)
#pragma unroll
            for (int q = 0; q < 4; q++) acc[mf][nf][q] = 0.0f;

    // ldmatrix lane-address components (halves, within a stage)
    const uint32_t a_lane_off =
        (uint32_t)((wm * 64 + (lane & 15)) * ASTRH + ((lane >> 4) << 3));
    const uint32_t b_lane_off =
        (uint32_t)((wn * 32 + (lane & 7) + (((lane >> 4) & 1) << 3)) * ASTRH +
                   (((lane >> 3) & 1) << 3));

    // per-stage copy: 128 rows x 8 chunks (16B) for each of A and B -> 4+4 per thread
    auto issue = [&](int kb, int s) {
        const uint32_t abase = smb + (uint32_t)(s * A_STAGE_H) * 2;
#pragma unroll
        for (int i = 0; i < 4; i++) {
            int j = tid + i * 256;
            int r = j >> 3, c8 = j & 7;
            cpasync16(abase + (uint32_t)(r * ASTRH + c8 * 8) * 2,
                      A + (size_t)(m0 + r) * DMODEL + kb * GKB + c8 * 8, 16);
        }
        const uint32_t bbase = smb + (uint32_t)(BOFFH + s * B_STAGE_H) * 2;
#pragma unroll
        for (int i = 0; i < 4; i++) {
            int j = tid + i * 256;
            int r = j >> 3, c8 = j & 7;
            int rn = n0 + r;
            int ok = (rn < VOCAB);
            int rsrc = ok ? rn : (VOCAB - 1);
            cpasync16(bbase + (uint32_t)(r * ASTRH + c8 * 8) * 2,
                      Bw + (size_t)rsrc * DMODEL + kb * GKB + c8 * 8, ok ? 16 : 0);
        }
        CP_COMMIT();
    };

    issue(0, 0);
    issue(1, 1);

    for (int kb = 0; kb < NKB; kb++) {
        const int s = kb % NSTAGE;
        if (kb + 2 < NKB) issue(kb + 2, (kb + 2) % NSTAGE); else CP_COMMIT();
        CP_WAIT2();        // 3 groups outstanding -> group kb complete
        __syncthreads();

        const uint32_t a_st = smb + (uint32_t)(s * A_STAGE_H + a_lane_off) * 2;
        const uint32_t b_st = smb + (uint32_t)(BOFFH + s * B_STAGE_H + b_lane_off) * 2;
#pragma unroll
        for (int sl = 0; sl < 4; sl++) {       // 4 x k16 slices
            const uint32_t ko = (uint32_t)(sl * 16) * 2;
            uint32_t af[4][4], bf[4][2];
#pragma unroll
            for (int mf = 0; mf < 4; mf++)
                ldsm_x4(af[mf], a_st + (uint32_t)(mf * 16 * ASTRH) * 2 + ko);
#pragma unroll
            for (int p = 0; p < 2; p++) {
                uint32_t r[4];
                ldsm_x4(r, b_st + (uint32_t)(p * 16 * ASTRH) * 2 + ko);
                bf[2 * p][0] = r[0]; bf[2 * p][1] = r[1];
                bf[2 * p + 1][0] = r[2]; bf[2 * p + 1][1] = r[3];
            }
#pragma unroll
            for (int mf = 0; mf < 4; mf++)
#pragma unroll
                for (int nf = 0; nf < 4; nf++)
                    mma_f16_16n8k16(acc[mf][nf], af[mf], bf[nf]);
        }
        __syncthreads();   // all warps done reading stage s
    }

    // epilogue: scalar 4B stores (VOCAB odd => no 8B alignment guarantee)
#pragma unroll
    for (int mf = 0; mf < 4; mf++) {
        const int row = m0 + wm * 64 + mf * 16 + lr;
#pragma unroll
        for (int nf = 0; nf < 4; nf++) {
            const int col = n0 + wn * 32 + nf * 8 + 2 * lc;
            float* c0p = C + (size_t)row * VOCAB + col;
            float* c2p = C + (size_t)(row + 8) * VOCAB + col;
            if (col + 1 < VOCAB) {
                c0p[0] = acc[mf][nf][0];
                c0p[1] = acc[mf][nf][1];
                c2p[0] = acc[mf][nf][2];
                c2p[1] = acc[mf][nf][3];
            } else if (col < VOCAB) {
                c0p[0] = acc[mf][nf][0];
                c2p[0] = acc[mf][nf][2];
            }
        }
    }
}

// ---------------------------------------------------------------------------
// Launch
// ---------------------------------------------------------------------------
extern "C" void kernel_launch(void* const* d_in, const int* in_sizes, int n_in,
                              void* d_out, int out_size) {
    const int*   idx   = (const int*)d_in[0];
    const float* Wemb  = (const float*)d_in[1];
    const float* G     = (const float*)d_in[2];
    const float* Win   = (const float*)d_in[3];
    const float* Wrec  = (const float*)d_in[4];
    const float* Wout  = (const float*)d_in[5];
    const float* gamma = (const float*)d_in[6];
    const float* beta  = (const float*)d_in[7];
    float* out = (float*)d_out;

    cudaFuncSetAttribute(k_gemm, cudaFuncAttributeMaxDynamicSharedMemorySize,
                         GEMM_SMEM);

    k_embed_route<<<NROWS / 8, 160>>>(idx, Wemb, G, Win);

    const size_t ng = ((size_t)VOCAB * DMODEL) / 8;
    const unsigned nrb = (unsigned)((ng + 255) / 256);
    k_roundscan<<<nrb + 1, 256>>>(Wemb, Wrec);   // last block = scan

    k_outln<<<NROWS, 256>>>(Wout, gamma, beta);

    __half *hptr, *wtptr;
    cudaGetSymbolAddress((void**)&hptr, g_h16);
    cudaGetSymbolAddress((void**)&wtptr, g_Wh);
    dim3 grid(NROWS / GTM, (VOCAB + GTN - 1) / GTN);   // (16, 393)
    k_gemm<<<grid, 256, GEMM_SMEM>>>(hptr, wtptr, out);
}

// round 10
// speedup vs baseline: 1.1062x; 1.1062x over previous
#include <cuda_runtime.h>
#include <cuda_fp16.h>
#include <cstdint>
#include <cstddef>

// ---------------------------------------------------------------------------
// Problem constants
// ---------------------------------------------------------------------------
#define VOCAB 50257
#define DMODEL 768
#define NEXP 4
#define RRANK 32
#define BATCH 4
#define SEQ 512
#define NROWS (BATCH * SEQ)   // 2048

// ---------------------------------------------------------------------------
// Scratch (static device buffers; no cudaMalloc allowed)
// ---------------------------------------------------------------------------
__device__ __align__(256) float  g_x[NROWS * DMODEL];
__device__ __align__(256) __half g_h16[NROWS * DMODEL];
__device__ __align__(256) float  g_P[NROWS * NEXP * RRANK];
__device__ __align__(256) float  g_C[NROWS * RRANK];
__device__ __align__(256) int    g_E[NROWS];
__device__ __align__(256) __half g_Wh[(size_t)VOCAB * DMODEL];  // fp16 W_emb

__device__ __forceinline__ uint32_t smem_u32(const void* p) {
    uint32_t a;
    asm("{ .reg .u64 t; cvta.to.shared.u64 t, %1; cvt.u32.u64 %0, t; }"
        : "=r"(a) : "l"(p));
    return a;
}

__device__ __forceinline__ void cpasync16(uint32_t dst, const void* src, int szbytes) {
    asm volatile("cp.async.cg.shared.global [%0], [%1], 16, %2;"
                 :: "r"(dst), "l"(src), "r"(szbytes));
}
#define CP_COMMIT() asm volatile("cp.async.commit_group;" ::: "memory")
#define CP_WAIT3()  asm volatile("cp.async.wait_group 3;" ::: "memory")

__device__ __forceinline__ void ldsm_x4(uint32_t* r, uint32_t addr) {
    asm volatile("ldmatrix.sync.aligned.m8n8.x4.shared.b16 {%0,%1,%2,%3}, [%4];"
                 : "=r"(r[0]), "=r"(r[1]), "=r"(r[2]), "=r"(r[3]) : "r"(addr));
}

// ---------------------------------------------------------------------------
// Kernel 1: embedding gather + routing scores + input projection (all experts)
// ---------------------------------------------------------------------------
__global__ __launch_bounds__(160) void k_embed_route(
    const int* __restrict__ idx, const float* __restrict__ Wemb,
    const float* __restrict__ G, const float* __restrict__ Win) {
    __shared__ float xs[8][DMODEL];
    __shared__ float ssc[8][NEXP];
    __shared__ int tok[8];
    const int tid = threadIdx.x;
    const int row0 = blockIdx.x * 8;

    if (tid < 8) tok[tid] = idx[row0 + tid];
    __syncthreads();
    for (int i = tid; i < 8 * DMODEL; i += 160) {
        int rr = i / DMODEL, d = i - rr * DMODEL;
        float v = Wemb[(size_t)tok[rr] * DMODEL + d];
        xs[rr][d] = v;
        g_x[(size_t)(row0 + rr) * DMODEL + d] = v;
    }
    __syncthreads();

    const int j = tid;
    if (j < 132) {
        float acc[8];
#pragma unroll
        for (int rr = 0; rr < 8; rr++) acc[rr] = 0.0f;
        const float* wp;
        int stride;
        if (j < 128) { int e = j >> 5, r = j & 31; wp = Win + (size_t)e * DMODEL * RRANK + r; stride = RRANK; }
        else         { wp = G + (size_t)(j - 128) * DMODEL; stride = 1; }
#pragma unroll 4
        for (int d = 0; d < DMODEL; d += 4) {
            float w0 = wp[(size_t)d * stride];
            float w1 = wp[(size_t)(d + 1) * stride];
            float w2 = wp[(size_t)(d + 2) * stride];
            float w3 = wp[(size_t)(d + 3) * stride];
#pragma unroll
            for (int rr = 0; rr < 8; rr++) {
                float4 xv = *(const float4*)&xs[rr][d];
                acc[rr] = fmaf(xv.x, w0, acc[rr]);
                acc[rr] = fmaf(xv.y, w1, acc[rr]);
                acc[rr] = fmaf(xv.z, w2, acc[rr]);
                acc[rr] = fmaf(xv.w, w3, acc[rr]);
            }
        }
        if (j < 128) {
#pragma unroll
            for (int rr = 0; rr < 8; rr++)
                g_P[(size_t)(row0 + rr) * (NEXP * RRANK) + j] = acc[rr];
        } else {
#pragma unroll
            for (int rr = 0; rr < 8; rr++) ssc[rr][j - 128] = acc[rr];
        }
    }
    __syncthreads();
    if (tid < 8) {
        float best = ssc[tid][0];
        int be = 0;
#pragma unroll
        for (int e = 1; e < NEXP; e++)
            if (ssc[tid][e] > best) { best = ssc[tid][e]; be = e; }
        g_E[row0 + tid] = be;
    }
}

// ---------------------------------------------------------------------------
// Kernel 2 (merged): W_emb fp32->fp16 rounding on blocks [0, N-4) and the
// recurrence on the last 4 blocks (one per batch).
//
// Scan parallelization: expert e's state changes ONLY at steps where e wins
// (sel gate), and cand_e is only consumed at those steps. So the 4 expert
// chains per batch are INDEPENDENT: warp e walks only its own winning steps
// (ballot-compacted list), total span = max_e(win count) instead of 512.
// ---------------------------------------------------------------------------
__global__ __launch_bounds__(256) void k_roundscan(
    const float* __restrict__ W, const float* __restrict__ Wrec) {
    if (blockIdx.x + 4 < gridDim.x) {
        // ---- rounding path: 8 elements per thread ----
        const size_t g = (size_t)blockIdx.x * 256 + threadIdx.x;
        const size_t ng = ((size_t)VOCAB * DMODEL) / 8;
        if (g >= ng) return;
        const float4 v0 = *((const float4*)W + g * 2);
        const float4 v1 = *((const float4*)W + g * 2 + 1);
        __half2 h[4];
        h[0] = __floats2half2_rn(v0.x, v0.y);
        h[1] = __floats2half2_rn(v0.z, v0.w);
        h[2] = __floats2half2_rn(v1.x, v1.y);
        h[3] = __floats2half2_rn(v1.z, v1.w);
        *((uint4*)g_Wh + g) = *(uint4*)h;
    } else {
        // ---- scan path: block = batch, warp = expert ----
        const int b = blockIdx.x - (gridDim.x - 4);
        const int tid = threadIdx.x;
        __shared__ int   esh[SEQ];        // winner per step
        __shared__ short tl[NEXP][SEQ];   // winning-step lists
        const int base = b * SEQ;
        for (int i = tid; i < SEQ; i += 256) esh[i] = g_E[base + i];
        __syncthreads();
        if (tid >= 128) return;
        const int e = tid >> 5;           // expert handled by this warp
        const int o = tid & 31;           // state component for this lane

        // ballot-compact the winning steps of expert e (ascending t)
        int cnt = 0;
        for (int c = 0; c < SEQ; c += 32) {
            const int t = c + o;
            const bool win = (esh[t] == e);
            const unsigned m = __ballot_sync(0xffffffffu, win);
            if (win) tl[e][cnt + __popc(m & ((1u << o) - 1))] = (short)t;
            cnt += __popc(m);
        }

        // per-lane recurrent weights: wr[k] = Wrec[e, k, o]
        float wr[32];
#pragma unroll
        for (int k = 0; k < 32; k++) wr[k] = Wrec[e * 1024 + k * 32 + o];

        float st = 0.f;
        float p_cur = (cnt > 0)
            ? g_P[(size_t)(base + tl[e][0]) * 128 + e * 32 + o] : 0.f;

        for (int i = 0; i < cnt; i++) {
            const float p_nxt = (i + 1 < cnt)
                ? g_P[(size_t)(base + tl[e][i + 1]) * 128 + e * 32 + o] : 0.f;
            float a0 = 0.f, a1 = 0.f, a2 = 0.f, a3 = 0.f;
#pragma unroll
            for (int k = 0; k < 8; k++) {
                a0 = fmaf(__shfl_sync(0xffffffffu, st, k     ), wr[k     ], a0);
                a1 = fmaf(__shfl_sync(0xffffffffu, st, k +  8), wr[k +  8], a1);
                a2 = fmaf(__shfl_sync(0xffffffffu, st, k + 16), wr[k + 16], a2);
                a3 = fmaf(__shfl_sync(0xffffffffu, st, k + 24), wr[k + 24], a3);
            }
            const float cand = tanhf(p_cur + ((a0 + a1) + (a2 + a3)));
            st = cand;
            g_C[(size_t)(base + tl[e][i]) * 32 + o] = cand;
            p_cur = p_nxt;
        }
    }
}

// ---------------------------------------------------------------------------
// Kernel 3: output projection + residual + LayerNorm -> fp16 h
// ---------------------------------------------------------------------------
__global__ __launch_bounds__(256) void k_outln(
    const float* __restrict__ Wout, const float* __restrict__ gamma,
    const float* __restrict__ beta) {
    __shared__ float csh[32];
    __shared__ float rs[8], rs2[8];
    const int row = blockIdx.x;
    const int tid = threadIdx.x;
    if (tid < 32) csh[tid] = g_C[(size_t)row * 32 + tid];
    const int e = g_E[row];
    __syncthreads();

    const float* wb = Wout + (size_t)e * RRANK * DMODEL;
    float y[3];
    float s = 0.f, s2 = 0.f;
#pragma unroll
    for (int ii = 0; ii < 3; ii++) {
        int d = tid + ii * 256;
        float acc = g_x[(size_t)row * DMODEL + d];
#pragma unroll
        for (int r = 0; r < 32; r++)
            acc = fmaf(csh[r], wb[r * DMODEL + d], acc);
        y[ii] = acc;
        s += acc;
        s2 = fmaf(acc, acc, s2);
    }
#pragma unroll
    for (int off = 16; off; off >>= 1) {
        s  += __shfl_xor_sync(0xffffffffu, s, off);
        s2 += __shfl_xor_sync(0xffffffffu, s2, off);
    }
    if ((tid & 31) == 0) { rs[tid >> 5] = s; rs2[tid >> 5] = s2; }
    __syncthreads();
    float S = 0.f, S2 = 0.f;
#pragma unroll
    for (int w = 0; w < 8; w++) { S += rs[w]; S2 += rs2[w]; }
    const float mean = S * (1.0f / DMODEL);
    const float var = S2 * (1.0f / DMODEL) - mean * mean;
    const float inv = rsqrtf(var + 1e-5f);
#pragma unroll
    for (int ii = 0; ii < 3; ii++) {
        int d = tid + ii * 256;
        float hv = (y[ii] - mean) * inv * gamma[d] + beta[d];
        g_h16[(size_t)row * DMODEL + d] = __float2half_rn(hv);
    }
}

// ---------------------------------------------------------------------------
// Kernel 4: logits = h @ W_emb^T, fp16 mma.sync.m16n8k16 (fp32 accumulate).
//   Round-8 config (best measured): CTA 128x256, 8 warps (2m x 4n),
//   warp tile 64x64, K chunk 64, 4-stage cp.async, ldmatrix fragments.
// ---------------------------------------------------------------------------
#define GTM 128
#define GTN 256
#define GKB 64
#define NKB (DMODEL / GKB)          // 12
#define ASTRH 72                    // halves per row
#define A_STAGE_H (GTM * ASTRH)     // 9216 halves
#define B_STAGE_H (GTN * ASTRH)     // 18432 halves
#define NSTAGE 4
#define BOFFH (NSTAGE * A_STAGE_H)
#define GEMM_SMEM (NSTAGE * (A_STAGE_H + B_STAGE_H) * 2)   // 221,184 B

__device__ __forceinline__ void mma_f16_16n8k16(
    float* c, const uint32_t* a, const uint32_t* b) {
    asm volatile(
        "mma.sync.aligned.m16n8k16.row.col.f32.f16.f16.f32 "
        "{%0,%1,%2,%3}, {%4,%5,%6,%7}, {%8,%9}, {%0,%1,%2,%3};"
        : "+f"(c[0]), "+f"(c[1]), "+f"(c[2]), "+f"(c[3])
        : "r"(a[0]), "r"(a[1]), "r"(a[2]), "r"(a[3]), "r"(b[0]), "r"(b[1]));
}

__global__ __launch_bounds__(256, 1) void k_gemm(
    const __half* __restrict__ A, const __half* __restrict__ Bw,
    float* __restrict__ C) {
    extern __shared__ __half smh[];
    const uint32_t smb = smem_u32(smh);

    const int tid = threadIdx.x;
    const int wid = tid >> 5, lane = tid & 31;
    const int wm = wid & 1, wn = wid >> 1;       // 2(m) x 4(n)
    const int lr = lane >> 2, lc = lane & 3;
    const int m0 = blockIdx.x * GTM;
    const int n0 = blockIdx.y * GTN;

    float acc[4][8][4];
#pragma unroll
    for (int mf = 0; mf < 4; mf++)
#pragma unroll
        for (int nf = 0; nf < 8; nf++)
#pragma unroll
            for (int q = 0; q < 4; q++) acc[mf][nf][q] = 0.0f;

    const uint32_t a_lane_off =
        (uint32_t)((wm * 64 + (lane & 15)) * ASTRH + ((lane >> 4) << 3));
    const uint32_t b_lane_off =
        (uint32_t)((wn * 64 + (lane & 7) + (((lane >> 4) & 1) << 3)) * ASTRH +
                   (((lane >> 3) & 1) << 3));

    auto issue = [&](int kb, int s) {
        const uint32_t abase = smb + (uint32_t)(s * A_STAGE_H) * 2;
#pragma unroll
        for (int i = 0; i < 4; i++) {
            int j = tid + i * 256;
            int r = j >> 3, c8 = j & 7;
            cpasync16(abase + (uint32_t)(r * ASTRH + c8 * 8) * 2,
                      A + (size_t)(m0 + r) * DMODEL + kb * GKB + c8 * 8, 16);
        }
        const uint32_t bbase = smb + (uint32_t)(BOFFH + s * B_STAGE_H) * 2;
#pragma unroll
        for (int i = 0; i < 8; i++) {
            int j = tid + i * 256;
            int r = j >> 3, c8 = j & 7;
            int rn = n0 + r;
            int ok = (rn < VOCAB);
            int rsrc = ok ? rn : (VOCAB - 1);
            cpasync16(bbase + (uint32_t)(r * ASTRH + c8 * 8) * 2,
                      Bw + (size_t)rsrc * DMODEL + kb * GKB + c8 * 8, ok ? 16 : 0);
        }
        CP_COMMIT();
    };

    issue(0, 0);
    issue(1, 1);
    issue(2, 2);

    for (int kb = 0; kb < NKB; kb++) {
        const int s = kb % NSTAGE;
        if (kb + 3 < NKB) issue(kb + 3, (kb + 3) % NSTAGE); else CP_COMMIT();
        CP_WAIT3();        // 4 groups outstanding -> group kb complete
        __syncthreads();

        const uint32_t a_st = smb + (uint32_t)(s * A_STAGE_H + a_lane_off) * 2;
        const uint32_t b_st = smb + (uint32_t)(BOFFH + s * B_STAGE_H + b_lane_off) * 2;
#pragma unroll
        for (int sl = 0; sl < 4; sl++) {       // 4 x k16 slices
            const uint32_t ko = (uint32_t)(sl * 16) * 2;
            uint32_t af[4][4], bf[8][2];
#pragma unroll
            for (int mf = 0; mf < 4; mf++)
                ldsm_x4(af[mf], a_st + (uint32_t)(mf * 16 * ASTRH) * 2 + ko);
#pragma unroll
            for (int p = 0; p < 4; p++) {
                uint32_t r[4];
                ldsm_x4(r, b_st + (uint32_t)(p * 16 * ASTRH) * 2 + ko);
                bf[2 * p][0] = r[0]; bf[2 * p][1] = r[1];
                bf[2 * p + 1][0] = r[2]; bf[2 * p + 1][1] = r[3];
            }
#pragma unroll
            for (int mf = 0; mf < 4; mf++)
#pragma unroll
                for (int nf = 0; nf < 8; nf++)
                    mma_f16_16n8k16(acc[mf][nf], af[mf], bf[nf]);
        }
        __syncthreads();   // all warps done reading stage s
    }

    // epilogue: scalar 4B stores (VOCAB odd => no 8B alignment guarantee)
#pragma unroll
    for (int mf = 0; mf < 4; mf++) {
        const int row = m0 + wm * 64 + mf * 16 + lr;
#pragma unroll
        for (int nf = 0; nf < 8; nf++) {
            const int col = n0 + wn * 64 + nf * 8 + 2 * lc;
            float* c0p = C + (size_t)row * VOCAB + col;
            float* c2p = C + (size_t)(row + 8) * VOCAB + col;
            if (col + 1 < VOCAB) {
                c0p[0] = acc[mf][nf][0];
                c0p[1] = acc[mf][nf][1];
                c2p[0] = acc[mf][nf][2];
                c2p[1] = acc[mf][nf][3];
            } else if (col < VOCAB) {
                c0p[0] = acc[mf][nf][0];
                c2p[0] = acc[mf][nf][2];
            }
        }
    }
}

// ---------------------------------------------------------------------------
// Launch
// ---------------------------------------------------------------------------
extern "C" void kernel_launch(void* const* d_in, const int* in_sizes, int n_in,
                              void* d_out, int out_size) {
    const int*   idx   = (const int*)d_in[0];
    const float* Wemb  = (const float*)d_in[1];
    const float* G     = (const float*)d_in[2];
    const float* Win   = (const float*)d_in[3];
    const float* Wrec  = (const float*)d_in[4];
    const float* Wout  = (const float*)d_in[5];
    const float* gamma = (const float*)d_in[6];
    const float* beta  = (const float*)d_in[7];
    float* out = (float*)d_out;

    cudaFuncSetAttribute(k_gemm, cudaFuncAttributeMaxDynamicSharedMemorySize,
                         GEMM_SMEM);

    k_embed_route<<<NROWS / 8, 160>>>(idx, Wemb, G, Win);

    const size_t ng = ((size_t)VOCAB * DMODEL) / 8;
    const unsigned nrb = (unsigned)((ng + 255) / 256);
    k_roundscan<<<nrb + 4, 256>>>(Wemb, Wrec);   // last 4 blocks = scan

    k_outln<<<NROWS, 256>>>(Wout, gamma, beta);

    __half *hptr, *wtptr;
    cudaGetSymbolAddress((void**)&hptr, g_h16);
    cudaGetSymbolAddress((void**)&wtptr, g_Wh);
    dim3 grid(NROWS / GTM, (VOCAB + GTN - 1) / GTN);   // (16, 197)
    k_gemm<<<grid, 256, GEMM_SMEM>>>(hptr, wtptr, out);
}

// round 11
// speedup vs baseline: 1.2714x; 1.1493x over previous
#include <cuda_runtime.h>
#include <cuda_fp16.h>
#include <cstdint>
#include <cstddef>

// ---------------------------------------------------------------------------
// Problem constants
// ---------------------------------------------------------------------------
#define VOCAB 50257
#define DMODEL 768
#define NEXP 4
#define RRANK 32
#define BATCH 4
#define SEQ 512
#define NROWS (BATCH * SEQ)   // 2048

// ---------------------------------------------------------------------------
// Scratch (static device buffers; no cudaMalloc allowed)
// ---------------------------------------------------------------------------
__device__ __align__(256) float  g_x[NROWS * DMODEL];
__device__ __align__(256) __half g_h16[NROWS * DMODEL];
__device__ __align__(256) float  g_P[NROWS * NEXP * RRANK];
__device__ __align__(256) float  g_C[NROWS * RRANK];
__device__ __align__(256) int    g_E[NROWS];
__device__ __align__(256) __half g_Wh[(size_t)VOCAB * DMODEL];  // fp16 W_emb

__device__ __forceinline__ uint32_t smem_u32(const void* p) {
    uint32_t a;
    asm("{ .reg .u64 t; cvta.to.shared.u64 t, %1; cvt.u32.u64 %0, t; }"
        : "=r"(a) : "l"(p));
    return a;
}

__device__ __forceinline__ void cpasync16(uint32_t dst, const void* src, int szbytes) {
    asm volatile("cp.async.cg.shared.global [%0], [%1], 16, %2;"
                 :: "r"(dst), "l"(src), "r"(szbytes));
}
#define CP_COMMIT() asm volatile("cp.async.commit_group;" ::: "memory")
#define CP_WAIT2()  asm volatile("cp.async.wait_group 2;" ::: "memory")

__device__ __forceinline__ void ldsm_x4(uint32_t* r, uint32_t addr) {
    asm volatile("ldmatrix.sync.aligned.m8n8.x4.shared.b16 {%0,%1,%2,%3}, [%4];"
                 : "=r"(r[0]), "=r"(r[1]), "=r"(r[2]), "=r"(r[3]) : "r"(addr));
}

// ---------------------------------------------------------------------------
// Kernel 1 (merged): blocks [0,256) do embedding gather + routing + input
// projection; blocks [256, ...) do W_emb fp32->fp16 rounding. The two are
// mutually independent -> one launch, runtime = max instead of sum.
// ---------------------------------------------------------------------------
#define EMB_BLOCKS (NROWS / 8)   // 256

__global__ __launch_bounds__(256) void k_embedround(
    const int* __restrict__ idx, const float* __restrict__ Wemb,
    const float* __restrict__ G, const float* __restrict__ Win) {
    if (blockIdx.x >= EMB_BLOCKS) {
        // ---- rounding path: 8 elements per thread ----
        const size_t g = (size_t)(blockIdx.x - EMB_BLOCKS) * 256 + threadIdx.x;
        const size_t ng = ((size_t)VOCAB * DMODEL) / 8;
        if (g >= ng) return;
        const float4 v0 = *((const float4*)Wemb + g * 2);
        const float4 v1 = *((const float4*)Wemb + g * 2 + 1);
        __half2 h[4];
        h[0] = __floats2half2_rn(v0.x, v0.y);
        h[1] = __floats2half2_rn(v0.z, v0.w);
        h[2] = __floats2half2_rn(v1.x, v1.y);
        h[3] = __floats2half2_rn(v1.z, v1.w);
        *((uint4*)g_Wh + g) = *(uint4*)h;
        return;
    }

    // ---- embed + route path ----
    __shared__ float xs[8][DMODEL];
    __shared__ float ssc[8][NEXP];
    __shared__ int tok[8];
    const int tid = threadIdx.x;
    const int row0 = blockIdx.x * 8;

    if (tid < 8) tok[tid] = idx[row0 + tid];
    __syncthreads();
    for (int i = tid; i < 8 * DMODEL; i += 256) {
        int rr = i / DMODEL, d = i - rr * DMODEL;
        float v = Wemb[(size_t)tok[rr] * DMODEL + d];
        xs[rr][d] = v;
        g_x[(size_t)(row0 + rr) * DMODEL + d] = v;
    }
    __syncthreads();

    const int j = tid;
    if (j < 132) {
        float acc[8];
#pragma unroll
        for (int rr = 0; rr < 8; rr++) acc[rr] = 0.0f;
        const float* wp;
        int stride;
        if (j < 128) { int e = j >> 5, r = j & 31; wp = Win + (size_t)e * DMODEL * RRANK + r; stride = RRANK; }
        else         { wp = G + (size_t)(j - 128) * DMODEL; stride = 1; }
#pragma unroll 4
        for (int d = 0; d < DMODEL; d += 4) {
            float w0 = wp[(size_t)d * stride];
            float w1 = wp[(size_t)(d + 1) * stride];
            float w2 = wp[(size_t)(d + 2) * stride];
            float w3 = wp[(size_t)(d + 3) * stride];
#pragma unroll
            for (int rr = 0; rr < 8; rr++) {
                float4 xv = *(const float4*)&xs[rr][d];
                acc[rr] = fmaf(xv.x, w0, acc[rr]);
                acc[rr] = fmaf(xv.y, w1, acc[rr]);
                acc[rr] = fmaf(xv.z, w2, acc[rr]);
                acc[rr] = fmaf(xv.w, w3, acc[rr]);
            }
        }
        if (j < 128) {
#pragma unroll
            for (int rr = 0; rr < 8; rr++)
                g_P[(size_t)(row0 + rr) * (NEXP * RRANK) + j] = acc[rr];
        } else {
#pragma unroll
            for (int rr = 0; rr < 8; rr++) ssc[rr][j - 128] = acc[rr];
        }
    }
    __syncthreads();
    if (tid < 8) {
        float best = ssc[tid][0];
        int be = 0;
#pragma unroll
        for (int e = 1; e < NEXP; e++)
            if (ssc[tid][e] > best) { best = ssc[tid][e]; be = e; }
        g_E[row0 + tid] = be;
    }
}

// ---------------------------------------------------------------------------
// Kernel 2: recurrence. Block = batch, warp = expert. Expert chains are
// independent (state only updates at winning steps; cand only consumed
// there), so each warp walks only its ballot-compacted winning-step list.
// ---------------------------------------------------------------------------
__global__ __launch_bounds__(256) void k_scan(const float* __restrict__ Wrec) {
    const int b = blockIdx.x;
    const int tid = threadIdx.x;
    __shared__ int   esh[SEQ];
    __shared__ short tl[NEXP][SEQ];
    const int base = b * SEQ;
    for (int i = tid; i < SEQ; i += 256) esh[i] = g_E[base + i];
    __syncthreads();
    if (tid >= 128) return;
    const int e = tid >> 5;
    const int o = tid & 31;

    int cnt = 0;
    for (int c = 0; c < SEQ; c += 32) {
        const int t = c + o;
        const bool win = (esh[t] == e);
        const unsigned m = __ballot_sync(0xffffffffu, win);
        if (win) tl[e][cnt + __popc(m & ((1u << o) - 1))] = (short)t;
        cnt += __popc(m);
    }

    float wr[32];
#pragma unroll
    for (int k = 0; k < 32; k++) wr[k] = Wrec[e * 1024 + k * 32 + o];

    float st = 0.f;
    float p_cur = (cnt > 0)
        ? g_P[(size_t)(base + tl[e][0]) * 128 + e * 32 + o] : 0.f;

    for (int i = 0; i < cnt; i++) {
        const float p_nxt = (i + 1 < cnt)
            ? g_P[(size_t)(base + tl[e][i + 1]) * 128 + e * 32 + o] : 0.f;
        float a0 = 0.f, a1 = 0.f, a2 = 0.f, a3 = 0.f;
#pragma unroll
        for (int k = 0; k < 8; k++) {
            a0 = fmaf(__shfl_sync(0xffffffffu, st, k     ), wr[k     ], a0);
            a1 = fmaf(__shfl_sync(0xffffffffu, st, k +  8), wr[k +  8], a1);
            a2 = fmaf(__shfl_sync(0xffffffffu, st, k + 16), wr[k + 16], a2);
            a3 = fmaf(__shfl_sync(0xffffffffu, st, k + 24), wr[k + 24], a3);
        }
        const float cand = tanhf(p_cur + ((a0 + a1) + (a2 + a3)));
        st = cand;
        g_C[(size_t)(base + tl[e][i]) * 32 + o] = cand;
        p_cur = p_nxt;
    }
}

// ---------------------------------------------------------------------------
// Kernel 3: output projection + residual + LayerNorm -> fp16 h
// ---------------------------------------------------------------------------
__global__ __launch_bounds__(256) void k_outln(
    const float* __restrict__ Wout, const float* __restrict__ gamma,
    const float* __restrict__ beta) {
    __shared__ float csh[32];
    __shared__ float rs[8], rs2[8];
    const int row = blockIdx.x;
    const int tid = threadIdx.x;
    if (tid < 32) csh[tid] = g_C[(size_t)row * 32 + tid];
    const int e = g_E[row];
    __syncthreads();

    const float* wb = Wout + (size_t)e * RRANK * DMODEL;
    float y[3];
    float s = 0.f, s2 = 0.f;
#pragma unroll
    for (int ii = 0; ii < 3; ii++) {
        int d = tid + ii * 256;
        float acc = g_x[(size_t)row * DMODEL + d];
#pragma unroll
        for (int r = 0; r < 32; r++)
            acc = fmaf(csh[r], wb[r * DMODEL + d], acc);
        y[ii] = acc;
        s += acc;
        s2 = fmaf(acc, acc, s2);
    }
#pragma unroll
    for (int off = 16; off; off >>= 1) {
        s  += __shfl_xor_sync(0xffffffffu, s, off);
        s2 += __shfl_xor_sync(0xffffffffu, s2, off);
    }
    if ((tid & 31) == 0) { rs[tid >> 5] = s; rs2[tid >> 5] = s2; }
    __syncthreads();
    float S = 0.f, S2 = 0.f;
#pragma unroll
    for (int w = 0; w < 8; w++) { S += rs[w]; S2 += rs2[w]; }
    const float mean = S * (1.0f / DMODEL);
    const float var = S2 * (1.0f / DMODEL) - mean * mean;
    const float inv = rsqrtf(var + 1e-5f);
#pragma unroll
    for (int ii = 0; ii < 3; ii++) {
        int d = tid + ii * 256;
        float hv = (y[ii] - mean) * inv * gamma[d] + beta[d];
        g_h16[(size_t)row * DMODEL + d] = __float2half_rn(hv);
    }
}

// ---------------------------------------------------------------------------
// Kernel 4: logits = h @ W_emb^T, fp16 mma.sync.m16n8k16 (fp32 accumulate).
//   Round-9 measured-best GEMM: CTA 128x128, 8 warps (2m x 4n), warp tile
//   64x32, 2 CTAs/SM (co-resident CTA hides epilogue/barrier exposure),
//   K chunk 64, 3-stage cp.async (110.6 KB smem/CTA), ldmatrix fragments.
// ---------------------------------------------------------------------------
#define GTM 128
#define GTN 128
#define GKB 64
#define NKB (DMODEL / GKB)          // 12
#define ASTRH 72                    // halves per row
#define A_STAGE_H (GTM * ASTRH)     // 9216 halves
#define B_STAGE_H (GTN * ASTRH)     // 9216 halves
#define NSTAGE 3
#define BOFFH (NSTAGE * A_STAGE_H)
#define GEMM_SMEM (NSTAGE * (A_STAGE_H + B_STAGE_H) * 2)   // 110,592 B

__device__ __forceinline__ void mma_f16_16n8k16(
    float* c, const uint32_t* a, const uint32_t* b) {
    asm volatile(
        "mma.sync.aligned.m16n8k16.row.col.f32.f16.f16.f32 "
        "{%0,%1,%2,%3}, {%4,%5,%6,%7}, {%8,%9}, {%0,%1,%2,%3};"
        : "+f"(c[0]), "+f"(c[1]), "+f"(c[2]), "+f"(c[3])
        : "r"(a[0]), "r"(a[1]), "r"(a[2]), "r"(a[3]), "r"(b[0]), "r"(b[1]));
}

__global__ __launch_bounds__(256, 2) void k_gemm(
    const __half* __restrict__ A, const __half* __restrict__ Bw,
    float* __restrict__ C) {
    extern __shared__ __half smh[];
    const uint32_t smb = smem_u32(smh);

    const int tid = threadIdx.x;
    const int wid = tid >> 5, lane = tid & 31;
    const int wm = wid & 1, wn = wid >> 1;       // 2(m) x 4(n)
    const int lr = lane >> 2, lc = lane & 3;
    const int m0 = blockIdx.x * GTM;
    const int n0 = blockIdx.y * GTN;

    float acc[4][4][4];
#pragma unroll
    for (int mf = 0; mf < 4; mf++)
#pragma unroll
        for (int nf = 0; nf < 4; nf++)
#pragma unroll
            for (int q = 0; q < 4; q++) acc[mf][nf][q] = 0.0f;

    const uint32_t a_lane_off =
        (uint32_t)((wm * 64 + (lane & 15)) * ASTRH + ((lane >> 4) << 3));
    const uint32_t b_lane_off =
        (uint32_t)((wn * 32 + (lane & 7) + (((lane >> 4) & 1) << 3)) * ASTRH +
                   (((lane >> 3) & 1) << 3));

    auto issue = [&](int kb, int s) {
        const uint32_t abase = smb + (uint32_t)(s * A_STAGE_H) * 2;
#pragma unroll
        for (int i = 0; i < 4; i++) {
            int j = tid + i * 256;
            int r = j >> 3, c8 = j & 7;
            cpasync16(abase + (uint32_t)(r * ASTRH + c8 * 8) * 2,
                      A + (size_t)(m0 + r) * DMODEL + kb * GKB + c8 * 8, 16);
        }
        const uint32_t bbase = smb + (uint32_t)(BOFFH + s * B_STAGE_H) * 2;
#pragma unroll
        for (int i = 0; i < 4; i++) {
            int j = tid + i * 256;
            int r = j >> 3, c8 = j & 7;
            int rn = n0 + r;
            int ok = (rn < VOCAB);
            int rsrc = ok ? rn : (VOCAB - 1);
            cpasync16(bbase + (uint32_t)(r * ASTRH + c8 * 8) * 2,
                      Bw + (size_t)rsrc * DMODEL + kb * GKB + c8 * 8, ok ? 16 : 0);
        }
        CP_COMMIT();
    };

    issue(0, 0);
    issue(1, 1);

    for (int kb = 0; kb < NKB; kb++) {
        const int s = kb % NSTAGE;
        if (kb + 2 < NKB) issue(kb + 2, (kb + 2) % NSTAGE); else CP_COMMIT();
        CP_WAIT2();        // 3 groups outstanding -> group kb complete
        __syncthreads();

        const uint32_t a_st = smb + (uint32_t)(s * A_STAGE_H + a_lane_off) * 2;
        const uint32_t b_st = smb + (uint32_t)(BOFFH + s * B_STAGE_H + b_lane_off) * 2;
#pragma unroll
        for (int sl = 0; sl < 4; sl++) {       // 4 x k16 slices
            const uint32_t ko = (uint32_t)(sl * 16) * 2;
            uint32_t af[4][4], bf[4][2];
#pragma unroll
            for (int mf = 0; mf < 4; mf++)
                ldsm_x4(af[mf], a_st + (uint32_t)(mf * 16 * ASTRH) * 2 + ko);
#pragma unroll
            for (int p = 0; p < 2; p++) {
                uint32_t r[4];
                ldsm_x4(r, b_st + (uint32_t)(p * 16 * ASTRH) * 2 + ko);
                bf[2 * p][0] = r[0]; bf[2 * p][1] = r[1];
                bf[2 * p + 1][0] = r[2]; bf[2 * p + 1][1] = r[3];
            }
#pragma unroll
            for (int mf = 0; mf < 4; mf++)
#pragma unroll
                for (int nf = 0; nf < 4; nf++)
                    mma_f16_16n8k16(acc[mf][nf], af[mf], bf[nf]);
        }
        __syncthreads();   // all warps done reading stage s
    }

    // epilogue: scalar 4B stores (VOCAB odd => no 8B alignment guarantee)
#pragma unroll
    for (int mf = 0; mf < 4; mf++) {
        const int row = m0 + wm * 64 + mf * 16 + lr;
#pragma unroll
        for (int nf = 0; nf < 4; nf++) {
            const int col = n0 + wn * 32 + nf * 8 + 2 * lc;
            float* c0p = C + (size_t)row * VOCAB + col;
            float* c2p = C + (size_t)(row + 8) * VOCAB + col;
            if (col + 1 < VOCAB) {
                c0p[0] = acc[mf][nf][0];
                c0p[1] = acc[mf][nf][1];
                c2p[0] = acc[mf][nf][2];
                c2p[1] = acc[mf][nf][3];
            } else if (col < VOCAB) {
                c0p[0] = acc[mf][nf][0];
                c2p[0] = acc[mf][nf][2];
            }
        }
    }
}

// ---------------------------------------------------------------------------
// Launch
// ---------------------------------------------------------------------------
extern "C" void kernel_launch(void* const* d_in, const int* in_sizes, int n_in,
                              void* d_out, int out_size) {
    const int*   idx   = (const int*)d_in[0];
    const float* Wemb  = (const float*)d_in[1];
    const float* G     = (const float*)d_in[2];
    const float* Win   = (const float*)d_in[3];
    const float* Wrec  = (const float*)d_in[4];
    const float* Wout  = (const float*)d_in[5];
    const float* gamma = (const float*)d_in[6];
    const float* beta  = (const float*)d_in[7];
    float* out = (float*)d_out;

    cudaFuncSetAttribute(k_gemm, cudaFuncAttributeMaxDynamicSharedMemorySize,
                         GEMM_SMEM);

    const size_t ng = ((size_t)VOCAB * DMODEL) / 8;
    const unsigned nrb = (unsigned)((ng + 255) / 256);
    k_embedround<<<EMB_BLOCKS + nrb, 256>>>(idx, Wemb, G, Win);
    k_scan<<<BATCH, 256>>>(Wrec);
    k_outln<<<NROWS, 256>>>(Wout, gamma, beta);

    __half *hptr, *wtptr;
    cudaGetSymbolAddress((void**)&hptr, g_h16);
    cudaGetSymbolAddress((void**)&wtptr, g_Wh);
    dim3 grid(NROWS / GTM, (VOCAB + GTN - 1) / GTN);   // (16, 393)
    k_gemm<<<grid, 256, GEMM_SMEM>>>(hptr, wtptr, out);
}

// round 13
// speedup vs baseline: 1.2983x; 1.0212x over previous
#include <cuda_runtime.h>
#include <cuda_fp16.h>
#include <cstdint>
#include <cstddef>

// ---------------------------------------------------------------------------
// Problem constants
// ---------------------------------------------------------------------------
#define VOCAB 50257
#define DMODEL 768
#define NEXP 4
#define RRANK 32
#define BATCH 4
#define SEQ 512
#define NROWS (BATCH * SEQ)   // 2048

// ---------------------------------------------------------------------------
// Scratch (static device buffers; no cudaMalloc allowed)
// ---------------------------------------------------------------------------
__device__ __align__(256) float  g_x[NROWS * DMODEL];
__device__ __align__(256) __half g_h16[NROWS * DMODEL];
__device__ __align__(256) float  g_P[NROWS * NEXP * RRANK];
__device__ __align__(256) float  g_C[NROWS * RRANK];
__device__ __align__(256) int    g_E[NROWS];
__device__ __align__(256) __half g_Wh[(size_t)VOCAB * DMODEL];  // fp16 W_emb

__device__ __forceinline__ uint32_t smem_u32(const void* p) {
    uint32_t a;
    asm("{ .reg .u64 t; cvta.to.shared.u64 t, %1; cvt.u32.u64 %0, t; }"
        : "=r"(a) : "l"(p));
    return a;
}

__device__ __forceinline__ void cpasync16(uint32_t dst, const void* src, int szbytes) {
    asm volatile("cp.async.cg.shared.global [%0], [%1], 16, %2;"
                 :: "r"(dst), "l"(src), "r"(szbytes));
}
#define CP_COMMIT() asm volatile("cp.async.commit_group;" ::: "memory")
#define CP_WAIT1()  asm volatile("cp.async.wait_group 1;" ::: "memory")
#define CP_WAIT0()  asm volatile("cp.async.wait_group 0;" ::: "memory")

__device__ __forceinline__ void ldsm_x4(uint32_t* r, uint32_t addr) {
    asm volatile("ldmatrix.sync.aligned.m8n8.x4.shared.b16 {%0,%1,%2,%3}, [%4];"
                 : "=r"(r[0]), "=r"(r[1]), "=r"(r[2]), "=r"(r[3]) : "r"(addr));
}

// streaming store: keep C writes from evicting A/B stripes out of L2
__device__ __forceinline__ void stg_cs(float* p, float v) {
    asm volatile("st.global.cs.f32 [%0], %1;" :: "l"(p), "f"(v));
}

// ---------------------------------------------------------------------------
// Kernel 1 (merged): blocks [0,256) do embedding gather + routing + input
// projection; blocks [256, ...) do W_emb fp32->fp16 rounding.
// ---------------------------------------------------------------------------
#define EMB_BLOCKS (NROWS / 8)   // 256

__global__ __launch_bounds__(256) void k_embedround(
    const int* __restrict__ idx, const float* __restrict__ Wemb,
    const float* __restrict__ G, const float* __restrict__ Win) {
    if (blockIdx.x >= EMB_BLOCKS) {
        const size_t g = (size_t)(blockIdx.x - EMB_BLOCKS) * 256 + threadIdx.x;
        const size_t ng = ((size_t)VOCAB * DMODEL) / 8;
        if (g >= ng) return;
        const float4 v0 = *((const float4*)Wemb + g * 2);
        const float4 v1 = *((const float4*)Wemb + g * 2 + 1);
        __half2 h[4];
        h[0] = __floats2half2_rn(v0.x, v0.y);
        h[1] = __floats2half2_rn(v0.z, v0.w);
        h[2] = __floats2half2_rn(v1.x, v1.y);
        h[3] = __floats2half2_rn(v1.z, v1.w);
        *((uint4*)g_Wh + g) = *(uint4*)h;
        return;
    }

    __shared__ float xs[8][DMODEL];
    __shared__ float ssc[8][NEXP];
    __shared__ int tok[8];
    const int tid = threadIdx.x;
    const int row0 = blockIdx.x * 8;

    if (tid < 8) tok[tid] = idx[row0 + tid];
    __syncthreads();
    for (int i = tid; i < 8 * DMODEL; i += 256) {
        int rr = i / DMODEL, d = i - rr * DMODEL;
        float v = Wemb[(size_t)tok[rr] * DMODEL + d];
        xs[rr][d] = v;
        g_x[(size_t)(row0 + rr) * DMODEL + d] = v;
    }
    __syncthreads();

    const int j = tid;
    if (j < 132) {
        float acc[8];
#pragma unroll
        for (int rr = 0; rr < 8; rr++) acc[rr] = 0.0f;
        const float* wp;
        int stride;
        if (j < 128) { int e = j >> 5, r = j & 31; wp = Win + (size_t)e * DMODEL * RRANK + r; stride = RRANK; }
        else         { wp = G + (size_t)(j - 128) * DMODEL; stride = 1; }
#pragma unroll 4
        for (int d = 0; d < DMODEL; d += 4) {
            float w0 = wp[(size_t)d * stride];
            float w1 = wp[(size_t)(d + 1) * stride];
            float w2 = wp[(size_t)(d + 2) * stride];
            float w3 = wp[(size_t)(d + 3) * stride];
#pragma unroll
            for (int rr = 0; rr < 8; rr++) {
                float4 xv = *(const float4*)&xs[rr][d];
                acc[rr] = fmaf(xv.x, w0, acc[rr]);
                acc[rr] = fmaf(xv.y, w1, acc[rr]);
                acc[rr] = fmaf(xv.z, w2, acc[rr]);
                acc[rr] = fmaf(xv.w, w3, acc[rr]);
            }
        }
        if (j < 128) {
#pragma unroll
            for (int rr = 0; rr < 8; rr++)
                g_P[(size_t)(row0 + rr) * (NEXP * RRANK) + j] = acc[rr];
        } else {
#pragma unroll
            for (int rr = 0; rr < 8; rr++) ssc[rr][j - 128] = acc[rr];
        }
    }
    __syncthreads();
    if (tid < 8) {
        float best = ssc[tid][0];
        int be = 0;
#pragma unroll
        for (int e = 1; e < NEXP; e++)
            if (ssc[tid][e] > best) { best = ssc[tid][e]; be = e; }
        g_E[row0 + tid] = be;
    }
}

// ---------------------------------------------------------------------------
// Kernel 2: recurrence. Block = batch, warp = expert (independent chains).
// ---------------------------------------------------------------------------
__global__ __launch_bounds__(256) void k_scan(const float* __restrict__ Wrec) {
    const int b = blockIdx.x;
    const int tid = threadIdx.x;
    __shared__ int   esh[SEQ];
    __shared__ short tl[NEXP][SEQ];
    const int base = b * SEQ;
    for (int i = tid; i < SEQ; i += 256) esh[i] = g_E[base + i];
    __syncthreads();
    if (tid >= 128) return;
    const int e = tid >> 5;
    const int o = tid & 31;

    int cnt = 0;
    for (int c = 0; c < SEQ; c += 32) {
        const int t = c + o;
        const bool win = (esh[t] == e);
        const unsigned m = __ballot_sync(0xffffffffu, win);
        if (win) tl[e][cnt + __popc(m & ((1u << o) - 1))] = (short)t;
        cnt += __popc(m);
    }

    float wr[32];
#pragma unroll
    for (int k = 0; k < 32; k++) wr[k] = Wrec[e * 1024 + k * 32 + o];

    float st = 0.f;
    float p_cur = (cnt > 0)
        ? g_P[(size_t)(base + tl[e][0]) * 128 + e * 32 + o] : 0.f;

    for (int i = 0; i < cnt; i++) {
        const float p_nxt = (i + 1 < cnt)
            ? g_P[(size_t)(base + tl[e][i + 1]) * 128 + e * 32 + o] : 0.f;
        float a0 = 0.f, a1 = 0.f, a2 = 0.f, a3 = 0.f;
#pragma unroll
        for (int k = 0; k < 8; k++) {
            a0 = fmaf(__shfl_sync(0xffffffffu, st, k     ), wr[k     ], a0);
            a1 = fmaf(__shfl_sync(0xffffffffu, st, k +  8), wr[k +  8], a1);
            a2 = fmaf(__shfl_sync(0xffffffffu, st, k + 16), wr[k + 16], a2);
            a3 = fmaf(__shfl_sync(0xffffffffu, st, k + 24), wr[k + 24], a3);
        }
        const float cand = tanhf(p_cur + ((a0 + a1) + (a2 + a3)));
        st = cand;
        g_C[(size_t)(base + tl[e][i]) * 32 + o] = cand;
        p_cur = p_nxt;
    }
}

// ---------------------------------------------------------------------------
// Kernel 3: output projection + residual + LayerNorm -> fp16 h
// ---------------------------------------------------------------------------
__global__ __launch_bounds__(256) void k_outln(
    const float* __restrict__ Wout, const float* __restrict__ gamma,
    const float* __restrict__ beta) {
    __shared__ float csh[32];
    __shared__ float rs[8], rs2[8];
    const int row = blockIdx.x;
    const int tid = threadIdx.x;
    if (tid < 32) csh[tid] = g_C[(size_t)row * 32 + tid];
    const int e = g_E[row];
    __syncthreads();

    const float* wb = Wout + (size_t)e * RRANK * DMODEL;
    float y[3];
    float s = 0.f, s2 = 0.f;
#pragma unroll
    for (int ii = 0; ii < 3; ii++) {
        int d = tid + ii * 256;
        float acc = g_x[(size_t)row * DMODEL + d];
#pragma unroll
        for (int r = 0; r < 32; r++)
            acc = fmaf(csh[r], wb[r * DMODEL + d], acc);
        y[ii] = acc;
        s += acc;
        s2 = fmaf(acc, acc, s2);
    }
#pragma unroll
    for (int off = 16; off; off >>= 1) {
        s  += __shfl_xor_sync(0xffffffffu, s, off);
        s2 += __shfl_xor_sync(0xffffffffu, s2, off);
    }
    if ((tid & 31) == 0) { rs[tid >> 5] = s; rs2[tid >> 5] = s2; }
    __syncthreads();
    float S = 0.f, S2 = 0.f;
#pragma unroll
    for (int w = 0; w < 8; w++) { S += rs[w]; S2 += rs2[w]; }
    const float mean = S * (1.0f / DMODEL);
    const float var = S2 * (1.0f / DMODEL) - mean * mean;
    const float inv = rsqrtf(var + 1e-5f);
#pragma unroll
    for (int ii = 0; ii < 3; ii++) {
        int d = tid + ii * 256;
        float hv = (y[ii] - mean) * inv * gamma[d] + beta[d];
        g_h16[(size_t)row * DMODEL + d] = __float2half_rn(hv);
    }
}

// ---------------------------------------------------------------------------
// Kernel 4: logits = h @ W_emb^T, fp16 mma.sync.m16n8k16 (fp32 accumulate).
//   CTA 128x128, 8 warps (2m x 4n), warp tile 64x32, 2 CTAs/SM, K chunk 64,
//   3-stage cp.async, ldmatrix fragments.
//   This round: ONE barrier per mainloop iteration (wait -> barrier ->
//   issue(kb+2) -> compute, no trailing barrier) and .cs streaming C stores.
// ---------------------------------------------------------------------------
#define GTM 128
#define GTN 128
#define GKB 64
#define NKB (DMODEL / GKB)          // 12
#define ASTRH 72                    // halves per row
#define A_STAGE_H (GTM * ASTRH)     // 9216 halves
#define B_STAGE_H (GTN * ASTRH)     // 9216 halves
#define NSTAGE 3
#define BOFFH (NSTAGE * A_STAGE_H)
#define GEMM_SMEM (NSTAGE * (A_STAGE_H + B_STAGE_H) * 2)   // 110,592 B

__device__ __forceinline__ void mma_f16_16n8k16(
    float* c, const uint32_t* a, const uint32_t* b) {
    asm volatile(
        "mma.sync.aligned.m16n8k16.row.col.f32.f16.f16.f32 "
        "{%0,%1,%2,%3}, {%4,%5,%6,%7}, {%8,%9}, {%0,%1,%2,%3};"
        : "+f"(c[0]), "+f"(c[1]), "+f"(c[2]), "+f"(c[3])
        : "r"(a[0]), "r"(a[1]), "r"(a[2]), "r"(a[3]), "r"(b[0]), "r"(b[1]));
}

__global__ __launch_bounds__(256, 2) void k_gemm(
    const __half* __restrict__ A, const __half* __restrict__ Bw,
    float* __restrict__ C) {
    extern __shared__ __half smh[];
    const uint32_t smb = smem_u32(smh);

    const int tid = threadIdx.x;
    const int wid = tid >> 5, lane = tid & 31;
    const int wm = wid & 1, wn = wid >> 1;       // 2(m) x 4(n)
    const int lr = lane >> 2, lc = lane & 3;
    const int m0 = blockIdx.x * GTM;
    const int n0 = blockIdx.y * GTN;

    float acc[4][4][4];
#pragma unroll
    for (int mf = 0; mf < 4; mf++)
#pragma unroll
        for (int nf = 0; nf < 4; nf++)
#pragma unroll
            for (int q = 0; q < 4; q++) acc[mf][nf][q] = 0.0f;

    const uint32_t a_lane_off =
        (uint32_t)((wm * 64 + (lane & 15)) * ASTRH + ((lane >> 4) << 3));
    const uint32_t b_lane_off =
        (uint32_t)((wn * 32 + (lane & 7) + (((lane >> 4) & 1) << 3)) * ASTRH +
                   (((lane >> 3) & 1) << 3));

    auto issue = [&](int kb, int s) {
        const uint32_t abase = smb + (uint32_t)(s * A_STAGE_H) * 2;
#pragma unroll
        for (int i = 0; i < 4; i++) {
            int j = tid + i * 256;
            int r = j >> 3, c8 = j & 7;
            cpasync16(abase + (uint32_t)(r * ASTRH + c8 * 8) * 2,
                      A + (size_t)(m0 + r) * DMODEL + kb * GKB + c8 * 8, 16);
        }
        const uint32_t bbase = smb + (uint32_t)(BOFFH + s * B_STAGE_H) * 2;
#pragma unroll
        for (int i = 0; i < 4; i++) {
            int j = tid + i * 256;
            int r = j >> 3, c8 = j & 7;
            int rn = n0 + r;
            int ok = (rn < VOCAB);
            int rsrc = ok ? rn : (VOCAB - 1);
            cpasync16(bbase + (uint32_t)(r * ASTRH + c8 * 8) * 2,
                      Bw + (size_t)rsrc * DMODEL + kb * GKB + c8 * 8, ok ? 16 : 0);
        }
        CP_COMMIT();
    };

    issue(0, 0);
    issue(1, 1);

    for (int kb = 0; kb < NKB; kb++) {
        const int s = kb % NSTAGE;
        // stage kb landed (own groups); allow 1 newer group in flight
        if (kb == NKB - 1) CP_WAIT0(); else CP_WAIT1();
        // single barrier: everyone's stage-kb copies visible AND everyone
        // finished reading stage kb-1 (compute of the previous iteration)
        __syncthreads();
        // now safe to overwrite stage (kb+2)%3 == (kb-1)%3
        if (kb + 2 < NKB) issue(kb + 2, (kb + 2) % NSTAGE);

        const uint32_t a_st = smb + (uint32_t)(s * A_STAGE_H + a_lane_off) * 2;
        const uint32_t b_st = smb + (uint32_t)(BOFFH + s * B_STAGE_H + b_lane_off) * 2;
#pragma unroll
        for (int sl = 0; sl < 4; sl++) {       // 4 x k16 slices
            const uint32_t ko = (uint32_t)(sl * 16) * 2;
            uint32_t af[4][4], bf[4][2];
#pragma unroll
            for (int mf = 0; mf < 4; mf++)
                ldsm_x4(af[mf], a_st + (uint32_t)(mf * 16 * ASTRH) * 2 + ko);
#pragma unroll
            for (int p = 0; p < 2; p++) {
                uint32_t r[4];
                ldsm_x4(r, b_st + (uint32_t)(p * 16 * ASTRH) * 2 + ko);
                bf[2 * p][0] = r[0]; bf[2 * p][1] = r[1];
                bf[2 * p + 1][0] = r[2]; bf[2 * p + 1][1] = r[3];
            }
#pragma unroll
            for (int mf = 0; mf < 4; mf++)
#pragma unroll
                for (int nf = 0; nf < 4; nf++)
                    mma_f16_16n8k16(acc[mf][nf], af[mf], bf[nf]);
        }
        // no trailing barrier: next iteration's barrier provides the guard
    }

    // epilogue: scalar 4B streaming stores (VOCAB odd => no 8B alignment)
#pragma unroll
    for (int mf = 0; mf < 4; mf++) {
        const int row = m0 + wm * 64 + mf * 16 + lr;
#pragma unroll
        for (int nf = 0; nf < 4; nf++) {
            const int col = n0 + wn * 32 + nf * 8 + 2 * lc;
            float* c0p = C + (size_t)row * VOCAB + col;
            float* c2p = C + (size_t)(row + 8) * VOCAB + col;
            if (col + 1 < VOCAB) {
                stg_cs(c0p,     acc[mf][nf][0]);
                stg_cs(c0p + 1, acc[mf][nf][1]);
                stg_cs(c2p,     acc[mf][nf][2]);
                stg_cs(c2p + 1, acc[mf][nf][3]);
            } else if (col < VOCAB) {
                stg_cs(c0p, acc[mf][nf][0]);
                stg_cs(c2p, acc[mf][nf][2]);
            }
        }
    }
}

// ---------------------------------------------------------------------------
// Launch
// ---------------------------------------------------------------------------
extern "C" void kernel_launch(void* const* d_in, const int* in_sizes, int n_in,
                              void* d_out, int out_size) {
    const int*   idx   = (const int*)d_in[0];
    const float* Wemb  = (const float*)d_in[1];
    const float* G     = (const float*)d_in[2];
    const float* Win   = (const float*)d_in[3];
    const float* Wrec  = (const float*)d_in[4];
    const float* Wout  = (const float*)d_in[5];
    const float* gamma = (const float*)d_in[6];
    const float* beta  = (const float*)d_in[7];
    float* out = (float*)d_out;

    cudaFuncSetAttribute(k_gemm, cudaFuncAttributeMaxDynamicSharedMemorySize,
                         GEMM_SMEM);

    const size_t ng = ((size_t)VOCAB * DMODEL) / 8;
    const unsigned nrb = (unsigned)((ng + 255) / 256);
    k_embedround<<<EMB_BLOCKS + nrb, 256>>>(idx, Wemb, G, Win);
    k_scan<<<BATCH, 256>>>(Wrec);
    k_outln<<<NROWS, 256>>>(Wout, gamma, beta);

    __half *hptr, *wtptr;
    cudaGetSymbolAddress((void**)&hptr, g_h16);
    cudaGetSymbolAddress((void**)&wtptr, g_Wh);
    dim3 grid(NROWS / GTM, (VOCAB + GTN - 1) / GTN);   // (16, 393)
    k_gemm<<<grid, 256, GEMM_SMEM>>>(hptr, wtptr, out);
}

// round 15
// speedup vs baseline: 1.3482x; 1.0384x over previous
#include <cuda_runtime.h>
#include <cuda_fp16.h>
#include <cstdint>
#include <cstddef>

// ---------------------------------------------------------------------------
// Problem constants
// ---------------------------------------------------------------------------
#define VOCAB 50257
#define DMODEL 768
#define NEXP 4
#define RRANK 32
#define BATCH 4
#define SEQ 512
#define NROWS (BATCH * SEQ)   // 2048

#define NGRP (((size_t)VOCAB * DMODEL) / 8)   // 4,824,672 rounding groups
#define GCHUNK (NGRP / 3)                     // exact: 1,608,224
#define RBLK ((unsigned)((GCHUNK + 255) / 256))

// ---------------------------------------------------------------------------
// Scratch (static device buffers; no cudaMalloc allowed)
// ---------------------------------------------------------------------------
__device__ __align__(256) float  g_x[NROWS * DMODEL];
__device__ __align__(256) __half g_h16[NROWS * DMODEL];
__device__ __align__(256) float  g_P[NROWS * NEXP * RRANK];
__device__ __align__(256) float  g_C[NROWS * RRANK];
__device__ __align__(256) int    g_E[NROWS];
__device__ __align__(256) __half g_Wh[(size_t)VOCAB * DMODEL];  // fp16 W_emb

__device__ __forceinline__ uint32_t smem_u32(const void* p) {
    uint32_t a;
    asm("{ .reg .u64 t; cvta.to.shared.u64 t, %1; cvt.u32.u64 %0, t; }"
        : "=r"(a) : "l"(p));
    return a;
}

__device__ __forceinline__ void cpasync16(uint32_t dst, const void* src, int szbytes) {
    asm volatile("cp.async.cg.shared.global [%0], [%1], 16, %2;"
                 :: "r"(dst), "l"(src), "r"(szbytes));
}
#define CP_COMMIT() asm volatile("cp.async.commit_group;" ::: "memory")
#define CP_WAIT1()  asm volatile("cp.async.wait_group 1;" ::: "memory")
#define CP_WAIT0()  asm volatile("cp.async.wait_group 0;" ::: "memory")

__device__ __forceinline__ void ldsm_x4(uint32_t* r, uint32_t addr) {
    asm volatile("ldmatrix.sync.aligned.m8n8.x4.shared.b16 {%0,%1,%2,%3}, [%4];"
                 : "=r"(r[0]), "=r"(r[1]), "=r"(r[2]), "=r"(r[3]) : "r"(addr));
}

__device__ __forceinline__ void stg_cs(float* p, float v) {
    asm volatile("st.global.cs.f32 [%0], %1;" :: "l"(p), "f"(v));
}

// rounding worker: convert group g (8 fp32 -> 8 fp16), bounds-checked
__device__ __forceinline__ void round_group(const float* __restrict__ W,
                                            size_t g, size_t gend) {
    if (g >= gend) return;
    const float4 v0 = *((const float4*)W + g * 2);
    const float4 v1 = *((const float4*)W + g * 2 + 1);
    __half2 h[4];
    h[0] = __floats2half2_rn(v0.x, v0.y);
    h[1] = __floats2half2_rn(v0.z, v0.w);
    h[2] = __floats2half2_rn(v1.x, v1.y);
    h[3] = __floats2half2_rn(v1.z, v1.w);
    *((uint4*)g_Wh + g) = *(uint4*)h;
}

// ---------------------------------------------------------------------------
// Kernel 1: embedding gather + routing + input projection (blocks [0,256)),
// rounding chunk 0 on the rest.
// ---------------------------------------------------------------------------
#define EMB_BLOCKS (NROWS / 8)   // 256

__global__ __launch_bounds__(256) void k_embedround(
    const int* __restrict__ idx, const float* __restrict__ Wemb,
    const float* __restrict__ G, const float* __restrict__ Win) {
    if (blockIdx.x >= EMB_BLOCKS) {
        const size_t g = (size_t)(blockIdx.x - EMB_BLOCKS) * 256 + threadIdx.x;
        round_group(Wemb, g, GCHUNK);
        return;
    }

    __shared__ float xs[8][DMODEL];
    __shared__ float ssc[8][NEXP];
    __shared__ int tok[8];
    const int tid = threadIdx.x;
    const int row0 = blockIdx.x * 8;

    if (tid < 8) tok[tid] = idx[row0 + tid];
    __syncthreads();
    for (int i = tid; i < 8 * DMODEL; i += 256) {
        int rr = i / DMODEL, d = i - rr * DMODEL;
        float v = Wemb[(size_t)tok[rr] * DMODEL + d];
        xs[rr][d] = v;
        g_x[(size_t)(row0 + rr) * DMODEL + d] = v;
    }
    __syncthreads();

    const int j = tid;
    if (j < 132) {
        float acc[8];
#pragma unroll
        for (int rr = 0; rr < 8; rr++) acc[rr] = 0.0f;
        const float* wp;
        int stride;
        if (j < 128) { int e = j >> 5, r = j & 31; wp = Win + (size_t)e * DMODEL * RRANK + r; stride = RRANK; }
        else         { wp = G + (size_t)(j - 128) * DMODEL; stride = 1; }
#pragma unroll 4
        for (int d = 0; d < DMODEL; d += 4) {
            float w0 = wp[(size_t)d * stride];
            float w1 = wp[(size_t)(d + 1) * stride];
            float w2 = wp[(size_t)(d + 2) * stride];
            float w3 = wp[(size_t)(d + 3) * stride];
#pragma unroll
            for (int rr = 0; rr < 8; rr++) {
                float4 xv = *(const float4*)&xs[rr][d];
                acc[rr] = fmaf(xv.x, w0, acc[rr]);
                acc[rr] = fmaf(xv.y, w1, acc[rr]);
                acc[rr] = fmaf(xv.z, w2, acc[rr]);
                acc[rr] = fmaf(xv.w, w3, acc[rr]);
            }
        }
        if (j < 128) {
#pragma unroll
            for (int rr = 0; rr < 8; rr++)
                g_P[(size_t)(row0 + rr) * (NEXP * RRANK) + j] = acc[rr];
        } else {
#pragma unroll
            for (int rr = 0; rr < 8; rr++) ssc[rr][j - 128] = acc[rr];
        }
    }
    __syncthreads();
    if (tid < 8) {
        float best = ssc[tid][0];
        int be = 0;
#pragma unroll
        for (int e = 1; e < NEXP; e++)
            if (ssc[tid][e] > best) { best = ssc[tid][e]; be = e; }
        g_E[row0 + tid] = be;
    }
}

// ---------------------------------------------------------------------------
// Kernel 2: recurrence on blocks [0,4) + rounding chunk 1 on the rest.
// ---------------------------------------------------------------------------
__global__ __launch_bounds__(256) void k_scan(
    const float* __restrict__ Wrec, const float* __restrict__ Wemb) {
    if (blockIdx.x >= BATCH) {
        const size_t g = GCHUNK +
            (size_t)(blockIdx.x - BATCH) * 256 + threadIdx.x;
        round_group(Wemb, g, 2 * GCHUNK);
        return;
    }
    const int b = blockIdx.x;
    const int tid = threadIdx.x;
    __shared__ int   esh[SEQ];
    __shared__ short tl[NEXP][SEQ];
    const int base = b * SEQ;
    for (int i = tid; i < SEQ; i += 256) esh[i] = g_E[base + i];
    __syncthreads();
    if (tid >= 128) return;
    const int e = tid >> 5;
    const int o = tid & 31;

    int cnt = 0;
    for (int c = 0; c < SEQ; c += 32) {
        const int t = c + o;
        const bool win = (esh[t] == e);
        const unsigned m = __ballot_sync(0xffffffffu, win);
        if (win) tl[e][cnt + __popc(m & ((1u << o) - 1))] = (short)t;
        cnt += __popc(m);
    }

    float wr[32];
#pragma unroll
    for (int k = 0; k < 32; k++) wr[k] = Wrec[e * 1024 + k * 32 + o];

    float st = 0.f;
    float p_cur = (cnt > 0)
        ? g_P[(size_t)(base + tl[e][0]) * 128 + e * 32 + o] : 0.f;

    for (int i = 0; i < cnt; i++) {
        const float p_nxt = (i + 1 < cnt)
            ? g_P[(size_t)(base + tl[e][i + 1]) * 128 + e * 32 + o] : 0.f;
        float a0 = 0.f, a1 = 0.f, a2 = 0.f, a3 = 0.f;
#pragma unroll
        for (int k = 0; k < 8; k++) {
            a0 = fmaf(__shfl_sync(0xffffffffu, st, k     ), wr[k     ], a0);
            a1 = fmaf(__shfl_sync(0xffffffffu, st, k +  8), wr[k +  8], a1);
            a2 = fmaf(__shfl_sync(0xffffffffu, st, k + 16), wr[k + 16], a2);
            a3 = fmaf(__shfl_sync(0xffffffffu, st, k + 24), wr[k + 24], a3);
        }
        const float cand = tanhf(p_cur + ((a0 + a1) + (a2 + a3)));
        st = cand;
        g_C[(size_t)(base + tl[e][i]) * 32 + o] = cand;
        p_cur = p_nxt;
    }
}

// ---------------------------------------------------------------------------
// Kernel 3: outproj + residual + LayerNorm on blocks [0,2048) + rounding
// chunk 2 on the rest.
// ---------------------------------------------------------------------------
__global__ __launch_bounds__(256) void k_outln(
    const float* __restrict__ Wout, const float* __restrict__ gamma,
    const float* __restrict__ beta, const float* __restrict__ Wemb) {
    if (blockIdx.x >= NROWS) {
        const size_t g = 2 * GCHUNK +
            (size_t)(blockIdx.x - NROWS) * 256 + threadIdx.x;
        round_group(Wemb, g, NGRP);
        return;
    }
    __shared__ float csh[32];
    __shared__ float rs[8], rs2[8];
    const int row = blockIdx.x;
    const int tid = threadIdx.x;
    if (tid < 32) csh[tid] = g_C[(size_t)row * 32 + tid];
    const int e = g_E[row];
    __syncthreads();

    const float* wb = Wout + (size_t)e * RRANK * DMODEL;
    float y[3];
    float s = 0.f, s2 = 0.f;
#pragma unroll
    for (int ii = 0; ii < 3; ii++) {
        int d = tid + ii * 256;
        float acc = g_x[(size_t)row * DMODEL + d];
#pragma unroll
        for (int r = 0; r < 32; r++)
            acc = fmaf(csh[r], wb[r * DMODEL + d], acc);
        y[ii] = acc;
        s += acc;
        s2 = fmaf(acc, acc, s2);
    }
#pragma unroll
    for (int off = 16; off; off >>= 1) {
        s  += __shfl_xor_sync(0xffffffffu, s, off);
        s2 += __shfl_xor_sync(0xffffffffu, s2, off);
    }
    if ((tid & 31) == 0) { rs[tid >> 5] = s; rs2[tid >> 5] = s2; }
    __syncthreads();
    float S = 0.f, S2 = 0.f;
#pragma unroll
    for (int w = 0; w < 8; w++) { S += rs[w]; S2 += rs2[w]; }
    const float mean = S * (1.0f / DMODEL);
    const float var = S2 * (1.0f / DMODEL) - mean * mean;
    const float inv = rsqrtf(var + 1e-5f);
#pragma unroll
    for (int ii = 0; ii < 3; ii++) {
        int d = tid + ii * 256;
        float hv = (y[ii] - mean) * inv * gamma[d] + beta[d];
        g_h16[(size_t)row * DMODEL + d] = __float2half_rn(hv);
    }
}

// ---------------------------------------------------------------------------
// Kernel 4: logits = h @ W_emb^T, fp16 mma.sync.m16n8k16 (fp32 accumulate).
//   CTA 128x128, 8 warps (2m x 4n), warp tile 64x32, 2 CTAs/SM, K chunk 64,
//   3-stage cp.async, ldmatrix fragments, single barrier/iter, .cs stores.
//   This round: copies issued at END of iteration so LDSMs enter the L1tex
//   wavefront queue AHEAD of the copy burst (copy drains under HMMA tail).
// ---------------------------------------------------------------------------
#define GTM 128
#define GTN 128
#define GKB 64
#define NKB (DMODEL / GKB)          // 12
#define ASTRH 72                    // halves per row
#define A_STAGE_H (GTM * ASTRH)     // 9216 halves
#define B_STAGE_H (GTN * ASTRH)     // 9216 halves
#define NSTAGE 3
#define BOFFH (NSTAGE * A_STAGE_H)
#define GEMM_SMEM (NSTAGE * (A_STAGE_H + B_STAGE_H) * 2)   // 110,592 B

__device__ __forceinline__ void mma_f16_16n8k16(
    float* c, const uint32_t* a, const uint32_t* b) {
    asm volatile(
        "mma.sync.aligned.m16n8k16.row.col.f32.f16.f16.f32 "
        "{%0,%1,%2,%3}, {%4,%5,%6,%7}, {%8,%9}, {%0,%1,%2,%3};"
        : "+f"(c[0]), "+f"(c[1]), "+f"(c[2]), "+f"(c[3])
        : "r"(a[0]), "r"(a[1]), "r"(a[2]), "r"(a[3]), "r"(b[0]), "r"(b[1]));
}

__global__ __launch_bounds__(256, 2) void k_gemm(
    const __half* __restrict__ A, const __half* __restrict__ Bw,
    float* __restrict__ C) {
    extern __shared__ __half smh[];
    const uint32_t smb = smem_u32(smh);

    const int tid = threadIdx.x;
    const int wid = tid >> 5, lane = tid & 31;
    const int wm = wid & 1, wn = wid >> 1;       // 2(m) x 4(n)
    const int lr = lane >> 2, lc = lane & 3;
    const int m0 = blockIdx.x * GTM;
    const int n0 = blockIdx.y * GTN;

    float acc[4][4][4];
#pragma unroll
    for (int mf = 0; mf < 4; mf++)
#pragma unroll
        for (int nf = 0; nf < 4; nf++)
#pragma unroll
            for (int q = 0; q < 4; q++) acc[mf][nf][q] = 0.0f;

    const uint32_t a_lane_off =
        (uint32_t)((wm * 64 + (lane & 15)) * ASTRH + ((lane >> 4) << 3));
    const uint32_t b_lane_off =
        (uint32_t)((wn * 32 + (lane & 7) + (((lane >> 4) & 1) << 3)) * ASTRH +
                   (((lane >> 3) & 1) << 3));

    auto issue = [&](int kb, int s) {
        const uint32_t abase = smb + (uint32_t)(s * A_STAGE_H) * 2;
#pragma unroll
        for (int i = 0; i < 4; i++) {
            int j = tid + i * 256;
            int r = j >> 3, c8 = j & 7;
            cpasync16(abase + (uint32_t)(r * ASTRH + c8 * 8) * 2,
                      A + (size_t)(m0 + r) * DMODEL + kb * GKB + c8 * 8, 16);
        }
        const uint32_t bbase = smb + (uint32_t)(BOFFH + s * B_STAGE_H) * 2;
#pragma unroll
        for (int i = 0; i < 4; i++) {
            int j = tid + i * 256;
            int r = j >> 3, c8 = j & 7;
            int rn = n0 + r;
            int ok = (rn < VOCAB);
            int rsrc = ok ? rn : (VOCAB - 1);
            cpasync16(bbase + (uint32_t)(r * ASTRH + c8 * 8) * 2,
                      Bw + (size_t)rsrc * DMODEL + kb * GKB + c8 * 8, ok ? 16 : 0);
        }
        CP_COMMIT();
    };

    issue(0, 0);
    issue(1, 1);

    for (int kb = 0; kb < NKB; kb++) {
        const int s = kb % NSTAGE;
        // groups outstanding at this point: kb .. kb+1 (issued at iter ends)
        if (kb == NKB - 1) CP_WAIT0(); else CP_WAIT1();
        // single barrier: stage-kb copies visible to all warps AND all warps
        // finished reading stage kb-1 (previous iteration's compute)
        __syncthreads();

        const uint32_t a_st = smb + (uint32_t)(s * A_STAGE_H + a_lane_off) * 2;
        const uint32_t b_st = smb + (uint32_t)(BOFFH + s * B_STAGE_H + b_lane_off) * 2;
#pragma unroll
        for (int sl = 0; sl < 4; sl++) {       // 4 x k16 slices
            const uint32_t ko = (uint32_t)(sl * 16) * 2;
            uint32_t af[4][4], bf[4][2];
#pragma unroll
            for (int mf = 0; mf < 4; mf++)
                ldsm_x4(af[mf], a_st + (uint32_t)(mf * 16 * ASTRH) * 2 + ko);
#pragma unroll
            for (int p = 0; p < 2; p++) {
                uint32_t r[4];
                ldsm_x4(r, b_st + (uint32_t)(p * 16 * ASTRH) * 2 + ko);
                bf[2 * p][0] = r[0]; bf[2 * p][1] = r[1];
                bf[2 * p + 1][0] = r[2]; bf[2 * p + 1][1] = r[3];
            }
#pragma unroll
            for (int mf = 0; mf < 4; mf++)
#pragma unroll
                for (int nf = 0; nf < 4; nf++)
                    mma_f16_16n8k16(acc[mf][nf], af[mf], bf[nf]);
        }

        // issue AFTER compute: overwrites stage (kb+2)%3 == (kb-1)%3, whose
        // readers all finished before this iteration's barrier. LDSMs above
        // queued ahead of this copy burst -> no fragment-load inflation.
        if (kb + 2 < NKB) issue(kb + 2, (kb + 2) % NSTAGE);
    }

    // epilogue: scalar 4B streaming stores (VOCAB odd => no 8B alignment)
#pragma unroll
    for (int mf = 0; mf < 4; mf++) {
        const int row = m0 + wm * 64 + mf * 16 + lr;
#pragma unroll
        for (int nf = 0; nf < 4; nf++) {
            const int col = n0 + wn * 32 + nf * 8 + 2 * lc;
            float* c0p = C + (size_t)row * VOCAB + col;
            float* c2p = C + (size_t)(row + 8) * VOCAB + col;
            if (col + 1 < VOCAB) {
                stg_cs(c0p,     acc[mf][nf][0]);
                stg_cs(c0p + 1, acc[mf][nf][1]);
                stg_cs(c2p,     acc[mf][nf][2]);
                stg_cs(c2p + 1, acc[mf][nf][3]);
            } else if (col < VOCAB) {
                stg_cs(c0p, acc[mf][nf][0]);
                stg_cs(c2p, acc[mf][nf][2]);
            }
        }
    }
}

// ---------------------------------------------------------------------------
// Launch
// ---------------------------------------------------------------------------
extern "C" void kernel_launch(void* const* d_in, const int* in_sizes, int n_in,
                              void* d_out, int out_size) {
    const int*   idx   = (const int*)d_in[0];
    const float* Wemb  = (const float*)d_in[1];
    const float* G     = (const float*)d_in[2];
    const float* Win   = (const float*)d_in[3];
    const float* Wrec  = (const float*)d_in[4];
    const float* Wout  = (const float*)d_in[5];
    const float* gamma = (const float*)d_in[6];
    const float* beta  = (const float*)d_in[7];
    float* out = (float*)d_out;

    cudaFuncSetAttribute(k_gemm, cudaFuncAttributeMaxDynamicSharedMemorySize,
                         GEMM_SMEM);

    k_embedround<<<EMB_BLOCKS + RBLK, 256>>>(idx, Wemb, G, Win);
    k_scan<<<BATCH + RBLK, 256>>>(Wrec, Wemb);
    k_outln<<<NROWS + RBLK, 256>>>(Wout, gamma, beta, Wemb);

    __half *hptr, *wtptr;
    cudaGetSymbolAddress((void**)&hptr, g_h16);
    cudaGetSymbolAddress((void**)&wtptr, g_Wh);
    dim3 grid(NROWS / GTM, (VOCAB + GTN - 1) / GTN);   // (16, 393)
    k_gemm<<<grid, 256, GEMM_SMEM>>>(hptr, wtptr, out);
}